// round 3
// baseline (speedup 1.0000x reference)
#include <cuda_runtime.h>
#include <cuda_fp16.h>
#include <math.h>

#define NN_NODES 100000
#define EE_EDGES 3200000
#define FDIM 256
#define CDIM 64
#define LN_EPS 1e-5

// ---------------- scratch (static device globals; no allocation) ----------------
__device__ int    g_deg_s[NN_NODES];
__device__ int    g_deg_d[NN_NODES];
__device__ float  g_norm_s[NN_NODES];
__device__ float  g_norm_d[NN_NODES];
__device__ int    g_row_off[NN_NODES + 1];
__device__ int    g_cursor[NN_NODES];
__device__ int    g_col[EE_EDGES];
__device__ __half g_x16[(size_t)NN_NODES * FDIM];   // fp16 input features
__device__ __half g_h16[(size_t)NN_NODES * FDIM];   // fp16 hidden
__device__ float  g_agg[(size_t)NN_NODES * FDIM];   // fp32 aggregate (GEMM A)
__device__ float  g_t[(size_t)NN_NODES * CDIM];     // fp32 layer-3 GEMM out
__device__ double g_stats[2];   // sum, sumsq
__device__ float  g_ln[2];      // mu, inv_std

// ---------------- setup kernels ----------------
__global__ void k_init() {
    int i = blockIdx.x * blockDim.x + threadIdx.x;
    if (i < NN_NODES) { g_deg_s[i] = 0; g_deg_d[i] = 0; }
    if (i == 0) { g_stats[0] = 0.0; g_stats[1] = 0.0; }
}

__global__ void k_degrees(const int* __restrict__ src, const int* __restrict__ dst) {
    int e = blockIdx.x * blockDim.x + threadIdx.x;
    if (e < EE_EDGES) {
        atomicAdd(&g_deg_s[src[e]], 1);
        atomicAdd(&g_deg_d[dst[e]], 1);
    }
}

__global__ void k_scan() {
    const int T = 1024;
    int t = threadIdx.x;
    const int chunk = (NN_NODES + T - 1) / T;
    int beg = t * chunk;
    int end = min(beg + chunk, NN_NODES);
    int local = 0;
    for (int i = beg; i < end; i++) local += g_deg_d[i];

    __shared__ int sh[T];
    sh[t] = local;
    __syncthreads();
    for (int off = 1; off < T; off <<= 1) {
        int v = (t >= off) ? sh[t - off] : 0;
        __syncthreads();
        sh[t] += v;
        __syncthreads();
    }
    int run = sh[t] - local;
    for (int i = beg; i < end; i++) {
        g_row_off[i] = run;
        g_cursor[i] = run;
        run += g_deg_d[i];
    }
    if (t == T - 1) g_row_off[NN_NODES] = sh[T - 1];

    for (int i = beg; i < end; i++) {
        g_norm_s[i] = rsqrtf((float)max(g_deg_s[i], 1));
        g_norm_d[i] = rsqrtf((float)max(g_deg_d[i], 1));
    }
}

__global__ void k_fill(const int* __restrict__ src, const int* __restrict__ dst) {
    int e = blockIdx.x * blockDim.x + threadIdx.x;
    if (e < EE_EDGES) {
        int p = atomicAdd(&g_cursor[dst[e]], 1);
        g_col[p] = src[e];
    }
}

// fp32 -> fp16 convert (8 elements/thread)
__global__ void k_cvt(const float* __restrict__ x, __half* __restrict__ y, int n8) {
    int i = blockIdx.x * blockDim.x + threadIdx.x;
    if (i >= n8) return;
    float4 a = reinterpret_cast<const float4*>(x)[i * 2];
    float4 b = reinterpret_cast<const float4*>(x)[i * 2 + 1];
    __half2 h[4];
    h[0] = __floats2half2_rn(a.x, a.y);
    h[1] = __floats2half2_rn(a.z, a.w);
    h[2] = __floats2half2_rn(b.x, b.y);
    h[3] = __floats2half2_rn(b.z, b.w);
    reinterpret_cast<float4*>(y)[i] = *reinterpret_cast<float4*>(h);
}

// ---------------- SpMM: pull (warp per dst row), fp16 features, fp32 accum ----------------
// out[i][:] = norm_d[i] * sum_{j in N(i)} norm_s[j] * LN(h[j][:])
template <bool LN>
__global__ void k_spmm256(const __half* __restrict__ hin, float* __restrict__ out) {
    int gw = (blockIdx.x * blockDim.x + threadIdx.x) >> 5;
    int lane = threadIdx.x & 31;
    if (gw >= NN_NODES) return;

    float mu = 0.f, inv = 1.f;
    if (LN) { mu = g_ln[0]; inv = g_ln[1]; }

    int s0 = g_row_off[gw], s1 = g_row_off[gw + 1];
    float acc[8];
#pragma unroll
    for (int t = 0; t < 8; t++) acc[t] = 0.f;

    const float4* __restrict__ h4 = reinterpret_cast<const float4*>(hin); // 8 halves each

    for (int base = s0; base < s1; base += 32) {
        int kk = base + lane;
        int j = 0; float sc = 0.f;
        if (kk < s1) { j = g_col[kk]; sc = g_norm_s[j]; }
        int cnt = min(32, s1 - base);
#pragma unroll 8
        for (int i = 0; i < cnt; i++) {
            int   jj = __shfl_sync(0xffffffffu, j, i);
            float sj = __shfl_sync(0xffffffffu, sc, i);
            float4 raw = h4[(size_t)jj * 32 + lane];    // 8 halves
            const __half2* hp = reinterpret_cast<const __half2*>(&raw);
            float2 f0 = __half22float2(hp[0]);
            float2 f1 = __half22float2(hp[1]);
            float2 f2 = __half22float2(hp[2]);
            float2 f3 = __half22float2(hp[3]);
            float sv = LN ? (sj * inv) : sj;
            if (LN) {
                acc[0] = fmaf(f0.x - mu, sv, acc[0]); acc[1] = fmaf(f0.y - mu, sv, acc[1]);
                acc[2] = fmaf(f1.x - mu, sv, acc[2]); acc[3] = fmaf(f1.y - mu, sv, acc[3]);
                acc[4] = fmaf(f2.x - mu, sv, acc[4]); acc[5] = fmaf(f2.y - mu, sv, acc[5]);
                acc[6] = fmaf(f3.x - mu, sv, acc[6]); acc[7] = fmaf(f3.y - mu, sv, acc[7]);
            } else {
                acc[0] = fmaf(f0.x, sv, acc[0]); acc[1] = fmaf(f0.y, sv, acc[1]);
                acc[2] = fmaf(f1.x, sv, acc[2]); acc[3] = fmaf(f1.y, sv, acc[3]);
                acc[4] = fmaf(f2.x, sv, acc[4]); acc[5] = fmaf(f2.y, sv, acc[5]);
                acc[6] = fmaf(f3.x, sv, acc[6]); acc[7] = fmaf(f3.y, sv, acc[7]);
            }
        }
    }
    float nd = g_norm_d[gw];
    float4 o0 = make_float4(acc[0] * nd, acc[1] * nd, acc[2] * nd, acc[3] * nd);
    float4 o1 = make_float4(acc[4] * nd, acc[5] * nd, acc[6] * nd, acc[7] * nd);
    float4* o4 = reinterpret_cast<float4*>(out);
    o4[(size_t)gw * 64 + lane * 2]     = o0;
    o4[(size_t)gw * 64 + lane * 2 + 1] = o1;
}

// ---------------- SpMM 64-wide (final layer, with bias) ----------------
__global__ void k_spmm64(const float* __restrict__ tin, const float* __restrict__ bias,
                         float* __restrict__ out) {
    int gw = (blockIdx.x * blockDim.x + threadIdx.x) >> 5;
    int lane = threadIdx.x & 31;
    if (gw >= NN_NODES) return;

    int s0 = g_row_off[gw], s1 = g_row_off[gw + 1];
    float2 a = make_float2(0.f, 0.f);
    const float2* __restrict__ t2 = reinterpret_cast<const float2*>(tin);

    for (int base = s0; base < s1; base += 32) {
        int kk = base + lane;
        int j = 0; float sc = 0.f;
        if (kk < s1) { j = g_col[kk]; sc = g_norm_s[j]; }
        int cnt = min(32, s1 - base);
#pragma unroll 8
        for (int i = 0; i < cnt; i++) {
            int   jj = __shfl_sync(0xffffffffu, j, i);
            float sj = __shfl_sync(0xffffffffu, sc, i);
            float2 v = t2[(size_t)jj * (CDIM / 2) + lane];
            a.x = fmaf(v.x, sj, a.x);
            a.y = fmaf(v.y, sj, a.y);
        }
    }
    float nd = g_norm_d[gw];
    float2 b = reinterpret_cast<const float2*>(bias)[lane];
    float2 o;
    o.x = fmaf(a.x, nd, b.x);
    o.y = fmaf(a.y, nd, b.y);
    reinterpret_cast<float2*>(out)[(size_t)gw * (CDIM / 2) + lane] = o;
}

// ---------------- 3xTF32 split tensor-core GEMM ----------------
// C[M,Nn] = op(A[M,K]) @ B[K,Nn], A split hi/lo, B split hi/lo, 3 MMA terms.
__device__ __forceinline__ unsigned f2tf32(float x) {
    unsigned r;
    asm("cvt.rna.tf32.f32 %0, %1;" : "=r"(r) : "f"(x));
    return r;
}

template <int BM, int BN, int WM, int WN, bool BIAS_RELU, bool STATS, bool LNA,
          bool A_HALF, bool C_HALF>
__global__ void k_gemm3x(const void* __restrict__ Ap, const float* __restrict__ B,
                         const float* __restrict__ bias, void* __restrict__ Cp,
                         int M, int Nn, int K) {
    constexpr int BK = 16;
    constexpr int LDA = BK + 8;          // 24
    constexpr int LDB = BN + 8;
    constexpr int NWARP = (BM / WM) * (BN / WN);
    constexpr int NT = NWARP * 32;
    constexpr int MFRAG = WM / 16;
    constexpr int NFRAG = WN / 8;

    __shared__ float As_hi[BM * LDA];
    __shared__ float As_lo[BM * LDA];
    __shared__ float Bs_hi[BK * LDB];
    __shared__ float Bs_lo[BK * LDB];

    const int tid  = threadIdx.x;
    const int lane = tid & 31;
    const int warp = tid >> 5;
    const int wm0 = (warp / (BN / WN)) * WM;
    const int wn0 = (warp % (BN / WN)) * WN;
    const int bm0 = blockIdx.x * BM;
    const int bn0 = blockIdx.y * BN;

    float mu = 0.f, inv = 1.f;
    if (LNA) { mu = g_ln[0]; inv = g_ln[1]; }

    float acc[MFRAG][NFRAG][4];
#pragma unroll
    for (int i = 0; i < MFRAG; i++)
#pragma unroll
        for (int j = 0; j < NFRAG; j++)
#pragma unroll
            for (int q = 0; q < 4; q++) acc[i][j][q] = 0.f;

    const int gr = lane >> 2;
    const int gc = lane & 3;

    // A staging indices: each thread loads 8 consecutive k of one row
    static_assert(BM * (BK / 8) == NT, "A stage mapping");
    const int am = tid / (BK / 8);
    const int aq = tid % (BK / 8);
    const int arow = bm0 + am;

    for (int k0 = 0; k0 < K; k0 += BK) {
        // ---- stage A (optional LN, split hi/lo) ----
        {
            float v[8];
            if (arow < M) {
                if (A_HALF) {
                    const __half* A16 = (const __half*)Ap;
                    float4 raw = *reinterpret_cast<const float4*>(&A16[(size_t)arow * K + k0 + aq * 8]);
                    const __half2* hp = reinterpret_cast<const __half2*>(&raw);
                    float2 f0 = __half22float2(hp[0]);
                    float2 f1 = __half22float2(hp[1]);
                    float2 f2 = __half22float2(hp[2]);
                    float2 f3 = __half22float2(hp[3]);
                    v[0] = f0.x; v[1] = f0.y; v[2] = f1.x; v[3] = f1.y;
                    v[4] = f2.x; v[5] = f2.y; v[6] = f3.x; v[7] = f3.y;
                } else {
                    const float* Af = (const float*)Ap;
                    float4 r0 = *reinterpret_cast<const float4*>(&Af[(size_t)arow * K + k0 + aq * 8]);
                    float4 r1 = *reinterpret_cast<const float4*>(&Af[(size_t)arow * K + k0 + aq * 8 + 4]);
                    v[0] = r0.x; v[1] = r0.y; v[2] = r0.z; v[3] = r0.w;
                    v[4] = r1.x; v[5] = r1.y; v[6] = r1.z; v[7] = r1.w;
                }
            } else {
#pragma unroll
                for (int t = 0; t < 8; t++) v[t] = 0.f;
            }
            float4 hi[2], lo[2];
#pragma unroll
            for (int t = 0; t < 8; t++) {
                float x = LNA ? (v[t] - mu) * inv : v[t];
                float h = __uint_as_float(f2tf32(x));
                float l = __uint_as_float(f2tf32(x - h));
                reinterpret_cast<float*>(hi)[t] = h;
                reinterpret_cast<float*>(lo)[t] = l;
            }
            *reinterpret_cast<float4*>(&As_hi[am * LDA + aq * 8])     = hi[0];
            *reinterpret_cast<float4*>(&As_hi[am * LDA + aq * 8 + 4]) = hi[1];
            *reinterpret_cast<float4*>(&As_lo[am * LDA + aq * 8])     = lo[0];
            *reinterpret_cast<float4*>(&As_lo[am * LDA + aq * 8 + 4]) = lo[1];
        }
        // ---- stage B (split hi/lo) ----
#pragma unroll
        for (int p = 0; p < (BK * BN / 4) / NT; p++) {
            int idx = tid + p * NT;
            int bk = idx / (BN / 4), bn4 = idx % (BN / 4);
            float4 vb = *reinterpret_cast<const float4*>(&B[(size_t)(k0 + bk) * Nn + bn0 + bn4 * 4]);
            float4 hi, lo;
            hi.x = __uint_as_float(f2tf32(vb.x)); lo.x = __uint_as_float(f2tf32(vb.x - hi.x));
            hi.y = __uint_as_float(f2tf32(vb.y)); lo.y = __uint_as_float(f2tf32(vb.y - hi.y));
            hi.z = __uint_as_float(f2tf32(vb.z)); lo.z = __uint_as_float(f2tf32(vb.z - hi.z));
            hi.w = __uint_as_float(f2tf32(vb.w)); lo.w = __uint_as_float(f2tf32(vb.w - hi.w));
            *reinterpret_cast<float4*>(&Bs_hi[bk * LDB + bn4 * 4]) = hi;
            *reinterpret_cast<float4*>(&Bs_lo[bk * LDB + bn4 * 4]) = lo;
        }
        __syncthreads();

#pragma unroll
        for (int ks = 0; ks < BK / 8; ks++) {
            const int kb = ks * 8;
            unsigned ah[MFRAG][4], al[MFRAG][4];
#pragma unroll
            for (int mi = 0; mi < MFRAG; mi++) {
                int r = wm0 + mi * 16 + gr;
                ah[mi][0] = __float_as_uint(As_hi[r * LDA + kb + gc]);
                ah[mi][1] = __float_as_uint(As_hi[(r + 8) * LDA + kb + gc]);
                ah[mi][2] = __float_as_uint(As_hi[r * LDA + kb + gc + 4]);
                ah[mi][3] = __float_as_uint(As_hi[(r + 8) * LDA + kb + gc + 4]);
                al[mi][0] = __float_as_uint(As_lo[r * LDA + kb + gc]);
                al[mi][1] = __float_as_uint(As_lo[(r + 8) * LDA + kb + gc]);
                al[mi][2] = __float_as_uint(As_lo[r * LDA + kb + gc + 4]);
                al[mi][3] = __float_as_uint(As_lo[(r + 8) * LDA + kb + gc + 4]);
            }
            unsigned bh[NFRAG][2], bl[NFRAG][2];
#pragma unroll
            for (int ni = 0; ni < NFRAG; ni++) {
                int c = wn0 + ni * 8 + gr;
                bh[ni][0] = __float_as_uint(Bs_hi[(kb + gc) * LDB + c]);
                bh[ni][1] = __float_as_uint(Bs_hi[(kb + gc + 4) * LDB + c]);
                bl[ni][0] = __float_as_uint(Bs_lo[(kb + gc) * LDB + c]);
                bl[ni][1] = __float_as_uint(Bs_lo[(kb + gc + 4) * LDB + c]);
            }
#pragma unroll
            for (int mi = 0; mi < MFRAG; mi++)
#pragma unroll
                for (int ni = 0; ni < NFRAG; ni++) {
#define MMA_TF32(A0,A1,A2,A3,B0,B1)                                              \
    asm volatile("mma.sync.aligned.m16n8k8.row.col.f32.tf32.tf32.f32 "           \
                 "{%0,%1,%2,%3}, {%4,%5,%6,%7}, {%8,%9}, {%0,%1,%2,%3};"         \
                 : "+f"(acc[mi][ni][0]), "+f"(acc[mi][ni][1]),                   \
                   "+f"(acc[mi][ni][2]), "+f"(acc[mi][ni][3])                    \
                 : "r"(A0), "r"(A1), "r"(A2), "r"(A3), "r"(B0), "r"(B1))
                    MMA_TF32(ah[mi][0], ah[mi][1], ah[mi][2], ah[mi][3], bl[ni][0], bl[ni][1]);
                    MMA_TF32(al[mi][0], al[mi][1], al[mi][2], al[mi][3], bh[ni][0], bh[ni][1]);
                    MMA_TF32(ah[mi][0], ah[mi][1], ah[mi][2], ah[mi][3], bh[ni][0], bh[ni][1]);
#undef MMA_TF32
                }
        }
        __syncthreads();
    }

    // ---- epilogue ----
    double psum = 0.0, psq = 0.0;
#pragma unroll
    for (int mi = 0; mi < MFRAG; mi++) {
#pragma unroll
        for (int ni = 0; ni < NFRAG; ni++) {
            int c0 = bn0 + wn0 + ni * 8 + gc * 2;
            float2 bb = make_float2(0.f, 0.f);
            if (BIAS_RELU) bb = *reinterpret_cast<const float2*>(&bias[c0]);
#pragma unroll
            for (int half = 0; half < 2; half++) {
                int row = bm0 + wm0 + mi * 16 + gr + half * 8;
                if (row >= M) continue;
                float x = acc[mi][ni][half * 2 + 0];
                float y = acc[mi][ni][half * 2 + 1];
                if (BIAS_RELU) {
                    x = fmaxf(x + bb.x, 0.f);
                    y = fmaxf(y + bb.y, 0.f);
                }
                if (C_HALF) {
                    __half* C16 = (__half*)Cp;
                    *reinterpret_cast<__half2*>(&C16[(size_t)row * Nn + c0]) =
                        __floats2half2_rn(x, y);
                } else {
                    float* Cf = (float*)Cp;
                    *reinterpret_cast<float2*>(&Cf[(size_t)row * Nn + c0]) = make_float2(x, y);
                }
                if (STATS) {
                    psum += (double)x + (double)y;
                    psq  += (double)x * x + (double)y * y;
                }
            }
        }
    }

    if (STATS) {
#pragma unroll
        for (int off = 16; off > 0; off >>= 1) {
            psum += __shfl_down_sync(0xffffffffu, psum, off);
            psq  += __shfl_down_sync(0xffffffffu, psq, off);
        }
        if (lane == 0) {
            atomicAdd(&g_stats[0], psum);
            atomicAdd(&g_stats[1], psq);
        }
    }
}

__global__ void k_finalize(double count) {
    double s = g_stats[0], ss = g_stats[1];
    double mu = s / count;
    double var = ss / count - mu * mu;
    g_ln[0] = (float)mu;
    g_ln[1] = (float)(1.0 / sqrt(var + (double)LN_EPS));
    g_stats[0] = 0.0;
    g_stats[1] = 0.0;
}

// ---------------- launch ----------------
extern "C" void kernel_launch(void* const* d_in, const int* in_sizes, int n_in,
                              void* d_out, int out_size) {
    const float* feat = (const float*)d_in[0];
    const int*   src  = (const int*)d_in[1];
    const int*   dst  = (const int*)d_in[2];
    const float* W0   = (const float*)d_in[3];
    const float* b0   = (const float*)d_in[4];
    const float* W1   = (const float*)d_in[5];
    const float* b1   = (const float*)d_in[6];
    const float* W2   = (const float*)d_in[7];
    const float* b2   = (const float*)d_in[8];
    float* out = (float*)d_out;

    __half *x16 = nullptr, *h16 = nullptr;
    float *agg = nullptr, *tbuf = nullptr;
    cudaGetSymbolAddress((void**)&x16, g_x16);
    cudaGetSymbolAddress((void**)&h16, g_h16);
    cudaGetSymbolAddress((void**)&agg, g_agg);
    cudaGetSymbolAddress((void**)&tbuf, g_t);

    const int NB_N = (NN_NODES + 255) / 256;
    const int NB_E = (EE_EDGES + 255) / 256;
    const int NB_W = (NN_NODES * 32 + 255) / 256;  // warp per row
    const int NB_C = ((NN_NODES * FDIM / 8) + 255) / 256;

    // setup: degrees, norms, CSR (by dst), fp16 features
    k_init<<<NB_N, 256>>>();
    k_degrees<<<NB_E, 256>>>(src, dst);
    k_scan<<<1, 1024>>>();
    k_fill<<<NB_E, 256>>>(src, dst);
    k_cvt<<<NB_C, 256>>>(feat, x16, NN_NODES * FDIM / 8);

    const int GM = (NN_NODES + 127) / 128;
    const double cnt = (double)NN_NODES * FDIM;

    // layer 1: agg = DAD*X ; h1 = relu(agg@W0 + b0) (+stats), h1 stored fp16
    k_spmm256<false><<<NB_W, 256>>>(x16, agg);
    k_gemm3x<128, 128, 64, 32, true, true, false, false, true>
        <<<dim3(GM, FDIM / 128), 256>>>(agg, W0, b0, h16, NN_NODES, FDIM, FDIM);
    k_finalize<<<1, 1>>>(cnt);

    // layer 2: agg = DAD*LN(h1) ; h2 = relu(agg@W1 + b1) (+stats), fp16
    k_spmm256<true><<<NB_W, 256>>>(h16, agg);
    k_gemm3x<128, 128, 64, 32, true, true, false, false, true>
        <<<dim3(GM, FDIM / 128), 256>>>(agg, W1, b1, h16, NN_NODES, FDIM, FDIM);
    k_finalize<<<1, 1>>>(cnt);

    // layer 3 (reordered): t = LN(h2)@W2 (fp32 out) ; out = DAD*t + b2
    k_gemm3x<128, 64, 64, 16, false, false, true, true, false>
        <<<dim3(GM, 1), 256>>>(h16, W2, nullptr, tbuf, NN_NODES, CDIM, FDIM);
    k_spmm64<<<NB_W, 256>>>(tbuf, b2, out);
}